// round 4
// baseline (speedup 1.0000x reference)
#include <cuda_runtime.h>
#include <math.h>

#define NL 51       // labels
#define NC 16       // channels
#define PC 17       // reduced layout: 16 sums + count
#define RS 160      // per-channel row stride in warp copy (3 planes * 51 = 153 -> 160)
#define CNT_OFF (RS * NC)          // 2560
#define COPY_SZ (CNT_OFF + 64)     // 2624 floats = 10.25KB per warp copy
#define BLK1 128
#define NWARP1 4
#define GRID1 740   // 5 CTAs/SM * 148 SMs
#define BLK2 256
#define GRID2 1184

static const long long CH_STRIDE = 1LL << 21;   // 32*256*256 floats per channel
static const int N4 = 1048576;                  // 4194304 voxels / 4

// Scratch (allocation-free rule: __device__ globals)
static __device__ float  g_part1[GRID1][NL][PC];
static __device__ float  g_part2[GRID2][NL];
static __device__ float  g_red[NL][PC];
static __device__ float  g_meanm[NL][PC];
static __device__ double g_inter;

__device__ __forceinline__ double blockReduceD(double v) {
    __shared__ double sh[32];
    int lane = threadIdx.x & 31, w = threadIdx.x >> 5;
    #pragma unroll
    for (int o = 16; o; o >>= 1) v += __shfl_down_sync(0xffffffffu, v, o);
    if (lane == 0) sh[w] = v;
    __syncthreads();
    int nw = (blockDim.x + 31) >> 5;
    v = (threadIdx.x < nw) ? sh[threadIdx.x] : 0.0;
    if (w == 0) {
        #pragma unroll
        for (int o = 16; o; o >>= 1) v += __shfl_down_sync(0xffffffffu, v, o);
    }
    return v; // valid on thread 0
}

// ---------------- Pass 1: per-label counts + channel sums (atomic-free) ----------------
__global__ void __launch_bounds__(BLK1) k_pass1(const float* __restrict__ pred,
                                                const int* __restrict__ gt) {
    __shared__ float s[NWARP1 * COPY_SZ];   // 41.0 KB
    for (int i = threadIdx.x; i < NWARP1 * COPY_SZ; i += BLK1) s[i] = 0.f;
    __syncthreads();

    float* sw = s + (threadIdx.x >> 5) * COPY_SZ;   // this warp's private copy
    const unsigned lt = (1u << (threadIdx.x & 31)) - 1u;

    int g = blockIdx.x * BLK1 + threadIdx.x;
    for (int i4 = g; i4 < N4; i4 += GRID1 * BLK1) {
        unsigned am = __activemask();
        int4 lv = ((const int4*)gt)[i4];
        unsigned m0 = __match_any_sync(am, lv.x);
        unsigned m1 = __match_any_sync(am, lv.y);
        unsigned m2 = __match_any_sync(am, lv.z);
        unsigned m3 = __match_any_sync(am, lv.w);
        int r0 = __popc(m0 & lt), r1 = __popc(m1 & lt);
        int r2 = __popc(m2 & lt), r3 = __popc(m3 & lt);

        // counts: one plain RMW per dup-group leader (distinct labels -> distinct cells)
        if (r0 == 0) sw[CNT_OFF + lv.x] += (float)__popc(m0);
        if (r1 == 0) sw[CNT_OFF + lv.y] += (float)__popc(m1);
        if (r2 == 0) sw[CNT_OFF + lv.z] += (float)__popc(m2);
        if (r3 == 0) sw[CNT_OFF + lv.w] += (float)__popc(m3);

        // plane assignment: ranks 0,1 -> plain planes; rank>=2 -> atomic-only plane 2
        bool p0 = r0 < 2, p1 = r1 < 2, p2 = r2 < 2, p3 = r3 < 2;
        int b0 = (p0 ? r0 : 2) * NL + lv.x;
        int b1 = (p1 ? r1 : 2) * NL + lv.y;
        int b2 = (p2 ? r2 : 2) * NL + lv.z;
        int b3 = (p3 ? r3 : 2) * NL + lv.w;

        size_t v0 = (size_t)i4 * 4;
        const float4* base = (const float4*)(pred + (v0 >> 21) * (NC * (size_t)CH_STRIDE)
                                                  + (v0 & (size_t)(CH_STRIDE - 1)));
        #pragma unroll
        for (int k = 0; k < NC; k++) {
            float4 p = base[(size_t)k * (CH_STRIDE / 4)];
            int off = k * RS;
            if (p0) sw[off + b0] += p.x; else atomicAdd(&sw[off + b0], p.x);
            if (p1) sw[off + b1] += p.y; else atomicAdd(&sw[off + b1], p.y);
            if (p2) sw[off + b2] += p.z; else atomicAdd(&sw[off + b2], p.z);
            if (p3) sw[off + b3] += p.w; else atomicAdd(&sw[off + b3], p.w);
        }
    }
    __syncthreads();

    // collapse 4 warp copies x 3 planes -> per-CTA [NL][PC] partial
    for (int i = threadIdx.x; i < NL * PC; i += BLK1) {
        int l = i / PC, v = i % PC;
        float t = 0.f;
        if (v < NC) {
            #pragma unroll
            for (int w = 0; w < NWARP1; w++) {
                const float* c = s + w * COPY_SZ + v * RS + l;
                t += c[0] + c[NL] + c[2 * NL];
            }
        } else {
            #pragma unroll
            for (int w = 0; w < NWARP1; w++) t += s[w * COPY_SZ + CNT_OFF + l];
        }
        (&g_part1[blockIdx.x][0][0])[i] = t;
    }
}

// ---------------- Reduce partials (double accumulation) ----------------
__global__ void k_reduce1() { // grid NL*PC, block 128
    int l = blockIdx.x / PC, v = blockIdx.x % PC;
    double acc = 0.0;
    for (int c = threadIdx.x; c < GRID1; c += 128) acc += (double)g_part1[c][l][v];
    acc = blockReduceD(acc);
    if (threadIdx.x == 0) g_red[l][v] = (float)acc;
}

// ---------------- Stats: means, norms, inter-similarity ----------------
__global__ void k_stats() {
    __shared__ float s_cmn[NL - 1][NC];
    int t = threadIdx.x;
    if (t < NL) {
        float cf = fmaxf(g_red[t][16], 1.f);
        float m[NC];
        float nrm2 = 0.f;
        #pragma unroll
        for (int k = 0; k < NC; k++) {
            m[k] = g_red[t][k] / cf;
            nrm2 += m[k] * m[k];
        }
        float mn = sqrtf(nrm2);
        #pragma unroll
        for (int k = 0; k < NC; k++) g_meanm[t][k] = m[k];
        g_meanm[t][16] = mn;
        if (t >= 1) {
            float inv = 1.f / fmaxf(mn, 1e-8f);
            #pragma unroll
            for (int k = 0; k < NC; k++) s_cmn[t - 1][k] = m[k] * inv;
        }
    }
    __syncthreads();

    double acc = 0.0;
    for (int p = t; p < 1225; p += blockDim.x) {
        int i = 0, rem = p;
        while (rem >= (NL - 2) - i) { rem -= (NL - 2) - i; i++; }
        int j = i + 1 + rem;
        float d = 0.f;
        #pragma unroll
        for (int k = 0; k < NC; k++) d += s_cmn[i][k] * s_cmn[j][k];
        d = fminf(fmaxf(d, 0.f), 1.f);
        acc += (double)d;
    }
    acc = blockReduceD(acc);
    if (t == 0) g_inter = acc / 1225.0;
}

// ---------------- Pass 2: per-voxel cosine vs label mean ----------------
__global__ void __launch_bounds__(BLK2) k_pass2(const float* __restrict__ pred,
                                                const int* __restrict__ gt) {
    __shared__ float sm[NL * PC];
    __shared__ float si[NL];
    for (int i = threadIdx.x; i < NL * PC; i += BLK2) sm[i] = (&g_meanm[0][0])[i];
    for (int i = threadIdx.x; i < NL; i += BLK2) si[i] = 0.f;
    __syncthreads();

    int g = blockIdx.x * BLK2 + threadIdx.x;
    for (int i4 = g; i4 < N4; i4 += GRID2 * BLK2) {
        int4 lv = ((const int4*)gt)[i4];
        int l0 = lv.x * PC, l1 = lv.y * PC, l2 = lv.z * PC, l3 = lv.w * PC;

        size_t v0 = (size_t)i4 * 4;
        const float4* base = (const float4*)(pred + (v0 >> 21) * (NC * (size_t)CH_STRIDE)
                                                  + (v0 & (size_t)(CH_STRIDE - 1)));
        float d0 = 0.f, d1 = 0.f, d2 = 0.f, d3 = 0.f;
        float q0 = 0.f, q1 = 0.f, q2 = 0.f, q3 = 0.f;
        #pragma unroll
        for (int k = 0; k < NC; k++) {
            float4 p = base[(size_t)k * (CH_STRIDE / 4)];
            d0 += p.x * sm[l0 + k]; q0 += p.x * p.x;
            d1 += p.y * sm[l1 + k]; q1 += p.y * p.y;
            d2 += p.z * sm[l2 + k]; q2 += p.z * p.z;
            d3 += p.w * sm[l3 + k]; q3 += p.w * p.w;
        }
        float c0 = __fdividef(d0, fmaxf(sqrtf(q0) * sm[l0 + 16], 1e-8f));
        float c1 = __fdividef(d1, fmaxf(sqrtf(q1) * sm[l1 + 16], 1e-8f));
        float c2 = __fdividef(d2, fmaxf(sqrtf(q2) * sm[l2 + 16], 1e-8f));
        float c3 = __fdividef(d3, fmaxf(sqrtf(q3) * sm[l3 + 16], 1e-8f));
        atomicAdd(&si[lv.x], c0);
        atomicAdd(&si[lv.y], c1);
        atomicAdd(&si[lv.z], c2);
        atomicAdd(&si[lv.w], c3);
    }
    __syncthreads();
    for (int i = threadIdx.x; i < NL; i += BLK2) g_part2[blockIdx.x][i] = si[i];
}

// ---------------- Final: intra mean + loss ----------------
__global__ void k_final(float* __restrict__ out) {
    __shared__ float s_inv[NL];
    int t = threadIdx.x;
    if (t < NL) s_inv[t] = 1.f / fmaxf(g_red[t][16], 1.f);
    __syncthreads();

    double acc = 0.0;
    for (int idx = t; idx < (NL - 1) * GRID2; idx += blockDim.x) {
        int l = idx % (NL - 1) + 1;
        int c = idx / (NL - 1);
        acc += (double)g_part2[c][l] * (double)s_inv[l];
    }
    acc = blockReduceD(acc);
    if (t == 0) out[0] = (float)(g_inter - acc / (double)(NL - 1));
}

extern "C" void kernel_launch(void* const* d_in, const int* in_sizes, int n_in,
                              void* d_out, int out_size) {
    const float* pred = (const float*)d_in[0];
    const int* gt = (const int*)d_in[1];
    float* out = (float*)d_out;

    k_pass1<<<GRID1, BLK1>>>(pred, gt);
    k_reduce1<<<NL * PC, 128>>>();
    k_stats<<<1, 256>>>();
    k_pass2<<<GRID2, BLK2>>>(pred, gt);
    k_final<<<1, 256>>>(out);
}

// round 5
// speedup vs baseline: 1.2114x; 1.2114x over previous
#include <cuda_runtime.h>
#include <math.h>

#define NL 51
#define NC 16
#define PC 17
#define GRID1 148
#define BLK1 256
#define GRID2 1184
#define BLK2 256
#define TILE 1024
#define NT 4096           // 4194304 voxels / 1024
#define ROWB 4112         // staged p row stride (bytes): 4096 + 16
#define CAP 32

static const long long CH_STRIDE = 1LL << 21;   // floats per channel plane

// dynamic smem layout (bytes)
#define P_OFF(b)  ((b) * 65792)                  // 16 rows * 4112 = 65792 per buf
#define GT_OFF(b) (131584 + (b) * 4096)
#define IDX_OFF   139776                         // ushort[51][32] = 3264
#define CUR_OFF   143040                         // int[51]
#define SS_OFF    143248                         // float[51][16]
#define SCNT_OFF  146512                         // float[51]
#define SMEM1     146944

#define CP_ASYNC16(dst, src) \
    asm volatile("cp.async.cg.shared.global [%0], [%1], 16;\n" :: "r"(dst), "l"(src))
#define CP_COMMIT() asm volatile("cp.async.commit_group;\n" ::: "memory")
#define CP_WAIT1()  asm volatile("cp.async.wait_group 1;\n" ::: "memory")
#define CP_WAIT0()  asm volatile("cp.async.wait_group 0;\n" ::: "memory")

// Scratch (allocation-free rule: __device__ globals)
static __device__ float  g_part1[GRID1][NL][PC];
static __device__ float  g_part2[GRID2][NL];
static __device__ float  g_red[NL][PC];
static __device__ float  g_meanm[NL][PC];
static __device__ double g_inter;

__device__ __forceinline__ double blockReduceD(double v) {
    __shared__ double sh[32];
    int lane = threadIdx.x & 31, w = threadIdx.x >> 5;
    #pragma unroll
    for (int o = 16; o; o >>= 1) v += __shfl_down_sync(0xffffffffu, v, o);
    if (lane == 0) sh[w] = v;
    __syncthreads();
    int nw = (blockDim.x + 31) >> 5;
    v = (threadIdx.x < nw) ? sh[threadIdx.x] : 0.0;
    if (w == 0) {
        #pragma unroll
        for (int o = 16; o; o >>= 1) v += __shfl_down_sync(0xffffffffu, v, o);
    }
    return v; // valid on thread 0
}

__device__ __forceinline__ void issue_tile(unsigned sm32, int t, int buf,
                                           const float* __restrict__ pred,
                                           const int* __restrict__ gt) {
    size_t v0 = (size_t)t * TILE;
    const char* psrc = (const char*)(pred + (v0 >> 21) * (NC * (size_t)CH_STRIDE)
                                          + (v0 & (size_t)(CH_STRIDE - 1)));
    int tid = threadIdx.x;
    #pragma unroll
    for (int it = 0; it < 16; it++) {
        int o = tid + it * BLK1;         // 0..4095
        int k = o >> 8, c = o & 255;
        unsigned dst = sm32 + P_OFF(buf) + k * ROWB + c * 16;
        const char* src = psrc + (size_t)k * ((size_t)CH_STRIDE * 4) + (size_t)c * 16;
        CP_ASYNC16(dst, src);
    }
    unsigned dstg = sm32 + GT_OFF(buf) + tid * 16;
    const char* srcg = (const char*)(gt + v0) + (size_t)tid * 16;
    CP_ASYNC16(dstg, srcg);
}

// ---------------- Pass 1: staged, binned, near-atomic-free segment sums ----------------
__global__ void __launch_bounds__(BLK1) k_pass1(const float* __restrict__ pred,
                                                const int* __restrict__ gt) {
    extern __shared__ char sm[];
    float* sS = (float*)(sm + SS_OFF);
    float* scnt = (float*)(sm + SCNT_OFF);
    int* cursor = (int*)(sm + CUR_OFF);
    unsigned short* sidx = (unsigned short*)(sm + IDX_OFF);
    const int tid = threadIdx.x;

    unsigned sm32;
    asm("{ .reg .u64 t; cvta.to.shared.u64 t, %1; cvt.u32.u64 %0, t; }"
        : "=r"(sm32) : "l"(sm));

    for (int i = tid; i < NL * NC; i += BLK1) sS[i] = 0.f;
    if (tid < NL) scnt[tid] = 0.f;
    __syncthreads();

    // prologue: load first tile into buf 0
    issue_tile(sm32, blockIdx.x, 0, pred, gt);
    CP_COMMIT();

    int i = 0;
    for (int t = blockIdx.x; t < NT; t += GRID1, i++) {
        int buf = i & 1;
        int tn = t + GRID1;
        if (tn < NT) {
            issue_tile(sm32, tn, buf ^ 1, pred, gt);
            CP_COMMIT();
            CP_WAIT1();
        } else {
            CP_WAIT0();
        }
        __syncthreads();

        if (tid < NL) cursor[tid] = 0;
        __syncthreads();

        // scatter: build per-label bins (1 atomic per voxel)
        int4 lv = *(const int4*)(sm + GT_OFF(buf) + tid * 16);
        int ls[4] = {lv.x, lv.y, lv.z, lv.w};
        #pragma unroll
        for (int q = 0; q < 4; q++) {
            int l = ls[q], v = tid * 4 + q;
            int r = atomicAdd(&cursor[l], 1);
            if (r < CAP) {
                sidx[l * CAP + r] = (unsigned short)v;
            } else {
                #pragma unroll
                for (int k = 0; k < NC; k++)
                    atomicAdd(&sS[l * NC + k],
                              *(const float*)(sm + P_OFF(buf) + k * ROWB + v * 4));
            }
        }
        __syncthreads();

        // gather: warp w owns labels l % 8 == w; register accumulation
        int lane = tid & 31, w = tid >> 5;
        int k = lane & 15, s = lane >> 4;
        for (int l = w; l < NL; l += 8) {
            int c = cursor[l];
            int cc = c < CAP ? c : CAP;
            float acc = 0.f;
            for (int j = s; j < cc; j += 2) {
                int vid = sidx[l * CAP + j];
                acc += *(const float*)(sm + P_OFF(buf) + k * ROWB + vid * 4);
            }
            __syncwarp();
            acc += __shfl_xor_sync(0xffffffffu, acc, 16);
            if (s == 0) sS[l * NC + k] += acc;
            if (lane == 0) scnt[l] += (float)c;
        }
        __syncthreads();   // protect buffer + cursor reuse
    }

    // epilogue: per-CTA partials
    for (int i2 = tid; i2 < NL * PC; i2 += BLK1) {
        int l = i2 / PC, v = i2 % PC;
        (&g_part1[blockIdx.x][0][0])[i2] = (v < NC) ? sS[l * NC + v] : scnt[l];
    }
}

// ---------------- Reduce partials (double accumulation) ----------------
__global__ void k_reduce1() { // grid NL*PC, block 128
    int l = blockIdx.x / PC, v = blockIdx.x % PC;
    double acc = 0.0;
    for (int c = threadIdx.x; c < GRID1; c += 128) acc += (double)g_part1[c][l][v];
    acc = blockReduceD(acc);
    if (threadIdx.x == 0) g_red[l][v] = (float)acc;
}

// ---------------- Stats: means, norms, inter-similarity ----------------
__global__ void k_stats() {
    __shared__ float s_cmn[NL - 1][NC];
    int t = threadIdx.x;
    if (t < NL) {
        float cf = fmaxf(g_red[t][16], 1.f);
        float m[NC];
        float nrm2 = 0.f;
        #pragma unroll
        for (int k = 0; k < NC; k++) {
            m[k] = g_red[t][k] / cf;
            nrm2 += m[k] * m[k];
        }
        float mn = sqrtf(nrm2);
        #pragma unroll
        for (int k = 0; k < NC; k++) g_meanm[t][k] = m[k];
        g_meanm[t][16] = mn;
        if (t >= 1) {
            float inv = 1.f / fmaxf(mn, 1e-8f);
            #pragma unroll
            for (int k = 0; k < NC; k++) s_cmn[t - 1][k] = m[k] * inv;
        }
    }
    __syncthreads();

    double acc = 0.0;
    for (int p = t; p < 1225; p += blockDim.x) {
        int i = 0, rem = p;
        while (rem >= (NL - 2) - i) { rem -= (NL - 2) - i; i++; }
        int j = i + 1 + rem;
        float d = 0.f;
        #pragma unroll
        for (int k = 0; k < NC; k++) d += s_cmn[i][k] * s_cmn[j][k];
        d = fminf(fmaxf(d, 0.f), 1.f);
        acc += (double)d;
    }
    acc = blockReduceD(acc);
    if (t == 0) g_inter = acc / 1225.0;
}

// ---------------- Pass 2: per-voxel cosine vs label mean ----------------
__global__ void __launch_bounds__(BLK2) k_pass2(const float* __restrict__ pred,
                                                const int* __restrict__ gt) {
    __shared__ float smn[NL * PC];
    __shared__ float si[NL];
    for (int i = threadIdx.x; i < NL * PC; i += BLK2) smn[i] = (&g_meanm[0][0])[i];
    for (int i = threadIdx.x; i < NL; i += BLK2) si[i] = 0.f;
    __syncthreads();

    const int N4 = 1048576;
    int g = blockIdx.x * BLK2 + threadIdx.x;
    for (int i4 = g; i4 < N4; i4 += GRID2 * BLK2) {
        int4 lv = ((const int4*)gt)[i4];
        int l0 = lv.x * PC, l1 = lv.y * PC, l2 = lv.z * PC, l3 = lv.w * PC;

        size_t v0 = (size_t)i4 * 4;
        const float4* base = (const float4*)(pred + (v0 >> 21) * (NC * (size_t)CH_STRIDE)
                                                  + (v0 & (size_t)(CH_STRIDE - 1)));
        float d0 = 0.f, d1 = 0.f, d2 = 0.f, d3 = 0.f;
        float q0 = 0.f, q1 = 0.f, q2 = 0.f, q3 = 0.f;
        #pragma unroll
        for (int k = 0; k < NC; k++) {
            float4 p = base[(size_t)k * (CH_STRIDE / 4)];
            d0 += p.x * smn[l0 + k]; q0 += p.x * p.x;
            d1 += p.y * smn[l1 + k]; q1 += p.y * p.y;
            d2 += p.z * smn[l2 + k]; q2 += p.z * p.z;
            d3 += p.w * smn[l3 + k]; q3 += p.w * p.w;
        }
        float c0 = __fdividef(d0, fmaxf(sqrtf(q0) * smn[l0 + 16], 1e-8f));
        float c1 = __fdividef(d1, fmaxf(sqrtf(q1) * smn[l1 + 16], 1e-8f));
        float c2 = __fdividef(d2, fmaxf(sqrtf(q2) * smn[l2 + 16], 1e-8f));
        float c3 = __fdividef(d3, fmaxf(sqrtf(q3) * smn[l3 + 16], 1e-8f));
        atomicAdd(&si[lv.x], c0);
        atomicAdd(&si[lv.y], c1);
        atomicAdd(&si[lv.z], c2);
        atomicAdd(&si[lv.w], c3);
    }
    __syncthreads();
    for (int i = threadIdx.x; i < NL; i += BLK2) g_part2[blockIdx.x][i] = si[i];
}

// ---------------- Final: intra mean + loss ----------------
__global__ void k_final(float* __restrict__ out) {
    __shared__ float s_inv[NL];
    int t = threadIdx.x;
    if (t < NL) s_inv[t] = 1.f / fmaxf(g_red[t][16], 1.f);
    __syncthreads();

    double acc = 0.0;
    for (int idx = t; idx < (NL - 1) * GRID2; idx += blockDim.x) {
        int l = idx % (NL - 1) + 1;
        int c = idx / (NL - 1);
        acc += (double)g_part2[c][l] * (double)s_inv[l];
    }
    acc = blockReduceD(acc);
    if (t == 0) out[0] = (float)(g_inter - acc / (double)(NL - 1));
}

extern "C" void kernel_launch(void* const* d_in, const int* in_sizes, int n_in,
                              void* d_out, int out_size) {
    const float* pred = (const float*)d_in[0];
    const int* gt = (const int*)d_in[1];
    float* out = (float*)d_out;

    cudaFuncSetAttribute(k_pass1, cudaFuncAttributeMaxDynamicSharedMemorySize, SMEM1);

    k_pass1<<<GRID1, BLK1, SMEM1>>>(pred, gt);
    k_reduce1<<<NL * PC, 128>>>();
    k_stats<<<1, 256>>>();
    k_pass2<<<GRID2, BLK2>>>(pred, gt);
    k_final<<<1, 256>>>(out);
}

// round 6
// speedup vs baseline: 1.4171x; 1.1698x over previous
#include <cuda_runtime.h>
#include <math.h>

#define NL 51
#define NC 16
#define PC 17
#define GRID1 148
#define BLK1 512
#define GRID2 1184
#define BLK2 256
#define TILE 1024
#define NT 4096           // 4194304 voxels / 1024
#define ROWB 4112         // staged p row stride (bytes)
#define CAP 32

static const long long CH_STRIDE = 1LL << 21;   // floats per channel plane

// dynamic smem layout (bytes)
#define P_OFF(b)  ((b) * 65792)                  // 16 rows * 4112
#define GT_OFF(b) (131584 + (b) * 4096)
#define IDX_OFF   139776                         // ushort[51][32]
#define CUR_OFF   143040                         // int[51]
#define SS_OFF    143248                         // float[51][16]
#define SCNT_OFF  146512                         // float[51]
#define SMEM1     146944

#define CP_ASYNC16(dst, src) \
    asm volatile("cp.async.cg.shared.global [%0], [%1], 16;\n" :: "r"(dst), "l"(src))
#define CP_COMMIT() asm volatile("cp.async.commit_group;\n" ::: "memory")
#define CP_WAIT1()  asm volatile("cp.async.wait_group 1;\n" ::: "memory")
#define CP_WAIT0()  asm volatile("cp.async.wait_group 0;\n" ::: "memory")

// Scratch (allocation-free rule: __device__ globals)
static __device__ float  g_part1[GRID1][NL][PC];
static __device__ float  g_part2[GRID2][NL];
static __device__ float  g_red[NL][PC];
static __device__ float  g_meanm[NL][PC];
static __device__ double g_inter;

__device__ __forceinline__ double blockReduceD(double v) {
    __shared__ double sh[32];
    int lane = threadIdx.x & 31, w = threadIdx.x >> 5;
    #pragma unroll
    for (int o = 16; o; o >>= 1) v += __shfl_down_sync(0xffffffffu, v, o);
    if (lane == 0) sh[w] = v;
    __syncthreads();
    int nw = (blockDim.x + 31) >> 5;
    v = (threadIdx.x < nw) ? sh[threadIdx.x] : 0.0;
    if (w == 0) {
        #pragma unroll
        for (int o = 16; o; o >>= 1) v += __shfl_down_sync(0xffffffffu, v, o);
    }
    return v; // valid on thread 0
}

__device__ __forceinline__ void issue_tile(unsigned sm32, int t, int buf,
                                           const float* __restrict__ pred,
                                           const int* __restrict__ gt) {
    size_t v0 = (size_t)t * TILE;
    const char* psrc = (const char*)(pred + (v0 >> 21) * (NC * (size_t)CH_STRIDE)
                                          + (v0 & (size_t)(CH_STRIDE - 1)));
    int tid = threadIdx.x;
    #pragma unroll
    for (int it = 0; it < 8; it++) {
        int o = tid + it * BLK1;         // 0..4095
        int k = o >> 8, c = o & 255;
        unsigned dst = sm32 + P_OFF(buf) + k * ROWB + c * 16;
        const char* src = psrc + (size_t)k * ((size_t)CH_STRIDE * 4) + (size_t)c * 16;
        CP_ASYNC16(dst, src);
    }
    if (tid < 256) {
        unsigned dstg = sm32 + GT_OFF(buf) + tid * 16;
        const char* srcg = (const char*)(gt + v0) + (size_t)tid * 16;
        CP_ASYNC16(dstg, srcg);
    }
}

// ---------------- Pass 1: staged, binned, 1-atomic-per-voxel segment sums ----------------
__global__ void __launch_bounds__(BLK1) k_pass1(const float* __restrict__ pred,
                                                const int* __restrict__ gt) {
    extern __shared__ char sm[];
    float* sS = (float*)(sm + SS_OFF);
    float* scnt = (float*)(sm + SCNT_OFF);
    int* cursor = (int*)(sm + CUR_OFF);
    unsigned short* sidx = (unsigned short*)(sm + IDX_OFF);
    const int tid = threadIdx.x;
    const int lane = tid & 31, w = tid >> 5;
    const int k = lane & 15, s = lane >> 4;

    unsigned sm32;
    asm("{ .reg .u64 t; cvta.to.shared.u64 t, %1; cvt.u32.u64 %0, t; }"
        : "=r"(sm32) : "l"(sm));

    for (int i = tid; i < NL * NC; i += BLK1) sS[i] = 0.f;
    if (tid < NL) scnt[tid] = 0.f;
    __syncthreads();

    issue_tile(sm32, blockIdx.x, 0, pred, gt);
    CP_COMMIT();

    int it = 0;
    for (int t = blockIdx.x; t < NT; t += GRID1, it++) {
        int buf = it & 1;
        int tn = t + GRID1;
        if (tn < NT) {
            issue_tile(sm32, tn, buf ^ 1, pred, gt);
            CP_COMMIT();
            CP_WAIT1();
        } else {
            CP_WAIT0();
        }
        __syncthreads();

        if (tid < NL) cursor[tid] = 0;
        __syncthreads();

        // scatter: build per-label bins (1 atomic per voxel), 2 voxels/thread
        int2 lv = *(const int2*)(sm + GT_OFF(buf) + tid * 8);
        int ls[2] = {lv.x, lv.y};
        #pragma unroll
        for (int q = 0; q < 2; q++) {
            int l = ls[q], v = tid * 2 + q;
            int r = atomicAdd(&cursor[l], 1);
            if (r < CAP) {
                sidx[l * CAP + r] = (unsigned short)v;
            } else {
                #pragma unroll
                for (int kk = 0; kk < NC; kk++)
                    atomicAdd(&sS[l * NC + kk],
                              *(const float*)(sm + P_OFF(buf) + kk * ROWB + v * 4));
            }
        }
        __syncthreads();

        // gather: warp w owns labels l % 16 == w; ushort4 vid prefetch, ILP-4
        const char* pbase = sm + P_OFF(buf) + k * ROWB;
        for (int l = w; l < NL; l += 16) {
            int c = cursor[l];
            int cc = c < CAP ? c : CAP;
            float acc = 0.f;
            #pragma unroll
            for (int jj = 0; jj < 4; jj++) {
                int i0 = s * 4 + jj * 8;
                if (i0 < cc) {
                    ushort4 v4 = *(const ushort4*)&sidx[l * CAP + i0];
                    acc += *(const float*)(pbase + (int)v4.x * 4);
                    if (i0 + 1 < cc) acc += *(const float*)(pbase + (int)v4.y * 4);
                    if (i0 + 2 < cc) acc += *(const float*)(pbase + (int)v4.z * 4);
                    if (i0 + 3 < cc) acc += *(const float*)(pbase + (int)v4.w * 4);
                }
            }
            acc += __shfl_xor_sync(0xffffffffu, acc, 16);
            if (s == 0) sS[l * NC + k] += acc;
            if (lane == 0) scnt[l] += (float)c;
        }
        __syncthreads();   // protect buffer + cursor reuse
    }

    for (int i2 = tid; i2 < NL * PC; i2 += BLK1) {
        int l = i2 / PC, v = i2 % PC;
        (&g_part1[blockIdx.x][0][0])[i2] = (v < NC) ? sS[l * NC + v] : scnt[l];
    }
}

// ---------------- Reduce partials (double accumulation) ----------------
__global__ void k_reduce1() { // grid NL*PC, block 128
    int l = blockIdx.x / PC, v = blockIdx.x % PC;
    double acc = 0.0;
    for (int c = threadIdx.x; c < GRID1; c += 128) acc += (double)g_part1[c][l][v];
    acc = blockReduceD(acc);
    if (threadIdx.x == 0) g_red[l][v] = (float)acc;
}

// ---------------- Stats: means, norms, inter-similarity ----------------
__global__ void k_stats() {
    __shared__ float s_cmn[NL - 1][NC];
    int t = threadIdx.x;
    if (t < NL) {
        float cf = fmaxf(g_red[t][16], 1.f);
        float m[NC];
        float nrm2 = 0.f;
        #pragma unroll
        for (int kk = 0; kk < NC; kk++) {
            m[kk] = g_red[t][kk] / cf;
            nrm2 += m[kk] * m[kk];
        }
        float mn = sqrtf(nrm2);
        #pragma unroll
        for (int kk = 0; kk < NC; kk++) g_meanm[t][kk] = m[kk];
        g_meanm[t][16] = mn;
        if (t >= 1) {
            float inv = 1.f / fmaxf(mn, 1e-8f);
            #pragma unroll
            for (int kk = 0; kk < NC; kk++) s_cmn[t - 1][kk] = m[kk] * inv;
        }
    }
    __syncthreads();

    double acc = 0.0;
    for (int p = t; p < 1225; p += blockDim.x) {
        int i = 0, rem = p;
        while (rem >= (NL - 2) - i) { rem -= (NL - 2) - i; i++; }
        int j = i + 1 + rem;
        float d = 0.f;
        #pragma unroll
        for (int kk = 0; kk < NC; kk++) d += s_cmn[i][kk] * s_cmn[j][kk];
        d = fminf(fmaxf(d, 0.f), 1.f);
        acc += (double)d;
    }
    acc = blockReduceD(acc);
    if (t == 0) g_inter = acc / 1225.0;
}

// ---------------- Pass 2: per-voxel cosine vs label mean ----------------
__global__ void __launch_bounds__(BLK2) k_pass2(const float* __restrict__ pred,
                                                const int* __restrict__ gt) {
    __shared__ float smn[NL * PC];
    __shared__ float si[NL];
    for (int i = threadIdx.x; i < NL * PC; i += BLK2) smn[i] = (&g_meanm[0][0])[i];
    for (int i = threadIdx.x; i < NL; i += BLK2) si[i] = 0.f;
    __syncthreads();

    const int N4 = 1048576;
    int g = blockIdx.x * BLK2 + threadIdx.x;
    for (int i4 = g; i4 < N4; i4 += GRID2 * BLK2) {
        int4 lv = ((const int4*)gt)[i4];
        int l0 = lv.x * PC, l1 = lv.y * PC, l2 = lv.z * PC, l3 = lv.w * PC;

        size_t v0 = (size_t)i4 * 4;
        const float4* base = (const float4*)(pred + (v0 >> 21) * (NC * (size_t)CH_STRIDE)
                                                  + (v0 & (size_t)(CH_STRIDE - 1)));
        float d0 = 0.f, d1 = 0.f, d2 = 0.f, d3 = 0.f;
        float q0 = 0.f, q1 = 0.f, q2 = 0.f, q3 = 0.f;
        #pragma unroll
        for (int kk = 0; kk < NC; kk++) {
            float4 p = base[(size_t)kk * (CH_STRIDE / 4)];
            d0 += p.x * smn[l0 + kk]; q0 += p.x * p.x;
            d1 += p.y * smn[l1 + kk]; q1 += p.y * p.y;
            d2 += p.z * smn[l2 + kk]; q2 += p.z * p.z;
            d3 += p.w * smn[l3 + kk]; q3 += p.w * p.w;
        }
        float c0 = __fdividef(d0, fmaxf(sqrtf(q0) * smn[l0 + 16], 1e-8f));
        float c1 = __fdividef(d1, fmaxf(sqrtf(q1) * smn[l1 + 16], 1e-8f));
        float c2 = __fdividef(d2, fmaxf(sqrtf(q2) * smn[l2 + 16], 1e-8f));
        float c3 = __fdividef(d3, fmaxf(sqrtf(q3) * smn[l3 + 16], 1e-8f));
        atomicAdd(&si[lv.x], c0);
        atomicAdd(&si[lv.y], c1);
        atomicAdd(&si[lv.z], c2);
        atomicAdd(&si[lv.w], c3);
    }
    __syncthreads();
    for (int i = threadIdx.x; i < NL; i += BLK2) g_part2[blockIdx.x][i] = si[i];
}

// ---------------- Final: intra mean + loss ----------------
__global__ void k_final(float* __restrict__ out) {
    __shared__ float s_inv[NL];
    int t = threadIdx.x;
    if (t < NL) s_inv[t] = 1.f / fmaxf(g_red[t][16], 1.f);
    __syncthreads();

    double acc = 0.0;
    for (int idx = t; idx < (NL - 1) * GRID2; idx += blockDim.x) {
        int l = idx % (NL - 1) + 1;
        int c = idx / (NL - 1);
        acc += (double)g_part2[c][l] * (double)s_inv[l];
    }
    acc = blockReduceD(acc);
    if (t == 0) out[0] = (float)(g_inter - acc / (double)(NL - 1));
}

extern "C" void kernel_launch(void* const* d_in, const int* in_sizes, int n_in,
                              void* d_out, int out_size) {
    const float* pred = (const float*)d_in[0];
    const int* gt = (const int*)d_in[1];
    float* out = (float*)d_out;

    cudaFuncSetAttribute(k_pass1, cudaFuncAttributeMaxDynamicSharedMemorySize, SMEM1);

    k_pass1<<<GRID1, BLK1, SMEM1>>>(pred, gt);
    k_reduce1<<<NL * PC, 128>>>();
    k_stats<<<1, 256>>>();
    k_pass2<<<GRID2, BLK2>>>(pred, gt);
    k_final<<<1, 256>>>(out);
}

// round 7
// speedup vs baseline: 2.0401x; 1.4396x over previous
#include <cuda_runtime.h>
#include <math.h>

#define NL 51
#define NC 16
#define PCX 33          // 16 sums + 16 normsums + count
#define GRID1 148
#define BLK1 512
#define TILE 1024
#define NT 4096         // 4194304 voxels / 1024
#define ROWB 4112       // staged p row stride (bytes)
#define CAP 32

static const long long CH_STRIDE = 1LL << 21;   // floats per channel plane

// dynamic smem layout (bytes)
#define P_OFF(b)   ((b) * 65792)                 // 16 rows * 4112
#define GT_OFF(b)  (131584 + (b) * 4096)
#define IDX_OFF    139776                        // ushort[51][32] = 3264
#define BINV_OFF   143040                        // float[51][32] = 6528
#define CUR_OFF    149568                        // int[51] -> 204, pad
#define SS_OFF     149776                        // float[51][16] = 3264
#define SN_OFF     153040                        // float[51][16] = 3264
#define SCNT_OFF   156304                        // float[51]
#define SMEM1      156544

#define CP_ASYNC16(dst, src) \
    asm volatile("cp.async.cg.shared.global [%0], [%1], 16;\n" :: "r"(dst), "l"(src))
#define CP_COMMIT() asm volatile("cp.async.commit_group;\n" ::: "memory")
#define CP_WAIT1()  asm volatile("cp.async.wait_group 1;\n" ::: "memory")
#define CP_WAIT0()  asm volatile("cp.async.wait_group 0;\n" ::: "memory")

// Scratch (allocation-free rule: __device__ globals)
static __device__ float g_part[GRID1][NL][PCX];
static __device__ float g_red[NL][PCX];

__device__ __forceinline__ double blockReduceD(double v) {
    __shared__ double sh[32];
    int lane = threadIdx.x & 31, w = threadIdx.x >> 5;
    #pragma unroll
    for (int o = 16; o; o >>= 1) v += __shfl_down_sync(0xffffffffu, v, o);
    if (lane == 0) sh[w] = v;
    __syncthreads();
    int nw = (blockDim.x + 31) >> 5;
    v = (threadIdx.x < nw) ? sh[threadIdx.x] : 0.0;
    if (w == 0) {
        #pragma unroll
        for (int o = 16; o; o >>= 1) v += __shfl_down_sync(0xffffffffu, v, o);
    }
    return v; // valid on thread 0
}

__device__ __forceinline__ void issue_tile(unsigned sm32, int t, int buf,
                                           const float* __restrict__ pred,
                                           const int* __restrict__ gt) {
    size_t v0 = (size_t)t * TILE;
    const char* psrc = (const char*)(pred + (v0 >> 21) * (NC * (size_t)CH_STRIDE)
                                          + (v0 & (size_t)(CH_STRIDE - 1)));
    int tid = threadIdx.x;
    #pragma unroll
    for (int it = 0; it < 8; it++) {
        int o = tid + it * BLK1;         // 0..4095
        int k = o >> 8, c = o & 255;
        unsigned dst = sm32 + P_OFF(buf) + k * ROWB + c * 16;
        const char* src = psrc + (size_t)k * ((size_t)CH_STRIDE * 4) + (size_t)c * 16;
        CP_ASYNC16(dst, src);
    }
    if (tid < 256) {
        unsigned dstg = sm32 + GT_OFF(buf) + tid * 16;
        const char* srcg = (const char*)(gt + v0) + (size_t)tid * 16;
        CP_ASYNC16(dstg, srcg);
    }
}

// ---------- Fused pass: per-label count, sum(p), sum(p/|p|) in ONE data read ----------
__global__ void __launch_bounds__(BLK1) k_fused(const float* __restrict__ pred,
                                                const int* __restrict__ gt) {
    extern __shared__ char sm[];
    float* sS = (float*)(sm + SS_OFF);
    float* sN = (float*)(sm + SN_OFF);
    float* scnt = (float*)(sm + SCNT_OFF);
    int* cursor = (int*)(sm + CUR_OFF);
    unsigned short* sidx = (unsigned short*)(sm + IDX_OFF);
    float* sbinv = (float*)(sm + BINV_OFF);
    const int tid = threadIdx.x;
    const int lane = tid & 31, w = tid >> 5;
    const int k = lane & 15, s = lane >> 4;

    unsigned sm32;
    asm("{ .reg .u64 t; cvta.to.shared.u64 t, %1; cvt.u32.u64 %0, t; }"
        : "=r"(sm32) : "l"(sm));

    for (int i = tid; i < NL * NC; i += BLK1) { sS[i] = 0.f; sN[i] = 0.f; }
    if (tid < NL) scnt[tid] = 0.f;
    __syncthreads();

    issue_tile(sm32, blockIdx.x, 0, pred, gt);
    CP_COMMIT();

    int it = 0;
    for (int t = blockIdx.x; t < NT; t += GRID1, it++) {
        int buf = it & 1;
        int tn = t + GRID1;
        if (tn < NT) {
            issue_tile(sm32, tn, buf ^ 1, pred, gt);
            CP_COMMIT();
            CP_WAIT1();
        } else {
            CP_WAIT0();
        }
        __syncthreads();

        if (tid < NL) cursor[tid] = 0;
        __syncthreads();

        // scatter + norm: 2 voxels/thread; inv-norms stay in registers
        int2 lv = *(const int2*)(sm + GT_OFF(buf) + tid * 8);
        float q0 = 0.f, q1 = 0.f;
        {
            const char* pb = sm + P_OFF(buf) + tid * 8;
            #pragma unroll
            for (int kk = 0; kk < NC; kk++) {
                float2 pp = *(const float2*)(pb + kk * ROWB);
                q0 += pp.x * pp.x;
                q1 += pp.y * pp.y;
            }
        }
        float inv0 = rsqrtf(fmaxf(q0, 1e-30f));
        float inv1 = rsqrtf(fmaxf(q1, 1e-30f));
        int ls[2] = {lv.x, lv.y};
        float iv[2] = {inv0, inv1};
        #pragma unroll
        for (int q = 0; q < 2; q++) {
            int l = ls[q], v = tid * 2 + q;
            float ivq = iv[q];
            int r = atomicAdd(&cursor[l], 1);
            if (r < CAP) {
                sidx[l * CAP + r] = (unsigned short)v;
                sbinv[l * CAP + r] = ivq;
            } else {
                #pragma unroll
                for (int kk = 0; kk < NC; kk++) {
                    float pv = *(const float*)(sm + P_OFF(buf) + kk * ROWB + v * 4);
                    atomicAdd(&sS[l * NC + kk], pv);
                    atomicAdd(&sN[l * NC + kk], pv * ivq);
                }
            }
        }
        __syncthreads();

        // gather: warp w owns labels l % 16 == w; dual accumulation, ILP-4
        const char* pbase = sm + P_OFF(buf) + k * ROWB;
        for (int l = w; l < NL; l += 16) {
            int c = cursor[l];
            int cc = c < CAP ? c : CAP;
            float ar = 0.f, an = 0.f;
            #pragma unroll
            for (int jj = 0; jj < 4; jj++) {
                int i0 = s * 4 + jj * 8;
                if (i0 < cc) {
                    ushort4 v4 = *(const ushort4*)&sidx[l * CAP + i0];
                    float4 n4 = *(const float4*)&sbinv[l * CAP + i0];
                    float p0 = *(const float*)(pbase + (int)v4.x * 4);
                    ar += p0; an += p0 * n4.x;
                    if (i0 + 1 < cc) {
                        float p1 = *(const float*)(pbase + (int)v4.y * 4);
                        ar += p1; an += p1 * n4.y;
                    }
                    if (i0 + 2 < cc) {
                        float p2 = *(const float*)(pbase + (int)v4.z * 4);
                        ar += p2; an += p2 * n4.z;
                    }
                    if (i0 + 3 < cc) {
                        float p3 = *(const float*)(pbase + (int)v4.w * 4);
                        ar += p3; an += p3 * n4.w;
                    }
                }
            }
            ar += __shfl_xor_sync(0xffffffffu, ar, 16);
            an += __shfl_xor_sync(0xffffffffu, an, 16);
            if (s == 0) {
                sS[l * NC + k] += ar;
                sN[l * NC + k] += an;
            }
            if (lane == 0) scnt[l] += (float)c;
        }
        __syncthreads();   // protect buffer + cursor reuse
    }

    for (int i2 = tid; i2 < NL * PCX; i2 += BLK1) {
        int l = i2 / PCX, v = i2 % PCX;
        float r;
        if (v < NC) r = sS[l * NC + v];
        else if (v < 2 * NC) r = sN[l * NC + (v - NC)];
        else r = scnt[l];
        (&g_part[blockIdx.x][0][0])[i2] = r;
    }
}

// ---------------- Reduce partials (double accumulation) ----------------
__global__ void k_reduce() { // grid NL*PCX, block 128
    int l = blockIdx.x / PCX, v = blockIdx.x % PCX;
    double acc = 0.0;
    for (int c = threadIdx.x; c < GRID1; c += 128) acc += (double)g_part[c][l][v];
    acc = blockReduceD(acc);
    if (threadIdx.x == 0) g_red[l][v] = (float)acc;
}

// ---------------- Finish: means, intra, inter, loss ----------------
__global__ void k_finish(float* __restrict__ out) {
    __shared__ float s_cmn[NL - 1][NC];
    int t = threadIdx.x;
    double intra_c = 0.0;
    if (t < NL) {
        float cf = fmaxf(g_red[t][32], 1.f);
        float m[NC];
        float n2 = 0.f;
        #pragma unroll
        for (int kk = 0; kk < NC; kk++) {
            m[kk] = g_red[t][kk] / cf;
            n2 += m[kk] * m[kk];
        }
        float mn = sqrtf(n2);
        if (t >= 1) {
            float inv = 1.f / fmaxf(mn, 1e-8f);
            float dot = 0.f;
            #pragma unroll
            for (int kk = 0; kk < NC; kk++) {
                s_cmn[t - 1][kk] = m[kk] * inv;
                dot += m[kk] * g_red[t][NC + kk];   // dot(m_l, sum of normalized p)
            }
            intra_c = (double)dot / ((double)fmaxf(mn, 1e-30f) * (double)cf);
        }
    }
    __syncthreads();
    double intra = blockReduceD(intra_c);   // valid on thread 0
    __syncthreads();

    double acc = 0.0;
    for (int p = t; p < 1225; p += blockDim.x) {
        int i = 0, rem = p;
        while (rem >= (NL - 2) - i) { rem -= (NL - 2) - i; i++; }
        int j = i + 1 + rem;
        float d = 0.f;
        #pragma unroll
        for (int kk = 0; kk < NC; kk++) d += s_cmn[i][kk] * s_cmn[j][kk];
        d = fminf(fmaxf(d, 0.f), 1.f);
        acc += (double)d;
    }
    __syncthreads();
    double inter = blockReduceD(acc);       // valid on thread 0
    if (t == 0) out[0] = (float)(inter / 1225.0 - intra / (double)(NL - 1));
}

extern "C" void kernel_launch(void* const* d_in, const int* in_sizes, int n_in,
                              void* d_out, int out_size) {
    const float* pred = (const float*)d_in[0];
    const int* gt = (const int*)d_in[1];
    float* out = (float*)d_out;

    cudaFuncSetAttribute(k_fused, cudaFuncAttributeMaxDynamicSharedMemorySize, SMEM1);

    k_fused<<<GRID1, BLK1, SMEM1>>>(pred, gt);
    k_reduce<<<NL * PCX, 128>>>();
    k_finish<<<1, 256>>>(out);
}

// round 8
// speedup vs baseline: 2.3332x; 1.1437x over previous
#include <cuda_runtime.h>
#include <math.h>

#define NL 51
#define NC 16
#define PCX 33          // 16 sums + 16 normsums + count
#define GRID1 296       // 2 CTAs/SM * 148
#define BLK1 256
#define TILE 512
#define NT 8192         // 4194304 voxels / 512
#define ROWB 2064       // staged p row stride (bytes): 512*4 + 16
#define CAP 32

static const long long CH_STRIDE = 1LL << 21;   // floats per channel plane

// dynamic smem layout (bytes)
#define P_OFF(b)   ((b) * 33024)                 // 16 rows * 2064
#define GT_OFF(b)  (66048 + (b) * 2048)
#define IDX_OFF    70144                         // ushort[51][32] = 3264
#define BINV_OFF   73408                         // float[51][32] = 6528
#define CUR_OFF    79936                         // int[51] + pad = 208
#define SS_OFF     80144                         // float[51][16] = 3264
#define SN_OFF     83408                         // float[51][16] = 3264
#define SCNT_OFF   86672                         // float[51] = 204
#define SMEM1      86912

#define CP_ASYNC16(dst, src) \
    asm volatile("cp.async.cg.shared.global [%0], [%1], 16;\n" :: "r"(dst), "l"(src))
#define CP_COMMIT() asm volatile("cp.async.commit_group;\n" ::: "memory")
#define CP_WAIT1()  asm volatile("cp.async.wait_group 1;\n" ::: "memory")
#define CP_WAIT0()  asm volatile("cp.async.wait_group 0;\n" ::: "memory")

// Scratch (allocation-free rule: __device__ globals)
static __device__ float g_part[GRID1][NL][PCX];
static __device__ float g_red[NL][PCX];

__device__ __forceinline__ double blockReduceD(double v) {
    __shared__ double sh[32];
    int lane = threadIdx.x & 31, w = threadIdx.x >> 5;
    #pragma unroll
    for (int o = 16; o; o >>= 1) v += __shfl_down_sync(0xffffffffu, v, o);
    if (lane == 0) sh[w] = v;
    __syncthreads();
    int nw = (blockDim.x + 31) >> 5;
    v = (threadIdx.x < nw) ? sh[threadIdx.x] : 0.0;
    if (w == 0) {
        #pragma unroll
        for (int o = 16; o; o >>= 1) v += __shfl_down_sync(0xffffffffu, v, o);
    }
    return v; // valid on thread 0
}

__device__ __forceinline__ void issue_tile(unsigned sm32, int t, int buf,
                                           const float* __restrict__ pred,
                                           const int* __restrict__ gt) {
    size_t v0 = (size_t)t * TILE;
    const char* psrc = (const char*)(pred + (v0 >> 21) * (NC * (size_t)CH_STRIDE)
                                          + (v0 & (size_t)(CH_STRIDE - 1)));
    int tid = threadIdx.x;
    #pragma unroll
    for (int it = 0; it < 8; it++) {
        int o = tid + it * BLK1;         // 0..2047
        int k = o >> 7, c = o & 127;     // 128 16B-granules per 512-float row
        unsigned dst = sm32 + P_OFF(buf) + k * ROWB + c * 16;
        const char* src = psrc + (size_t)k * ((size_t)CH_STRIDE * 4) + (size_t)c * 16;
        CP_ASYNC16(dst, src);
    }
    if (tid < 128) {
        unsigned dstg = sm32 + GT_OFF(buf) + tid * 16;
        const char* srcg = (const char*)(gt + v0) + (size_t)tid * 16;
        CP_ASYNC16(dstg, srcg);
    }
}

// ---------- Fused pass: per-label count, sum(p), sum(p/|p|) in ONE data read ----------
__global__ void __launch_bounds__(BLK1) k_fused(const float* __restrict__ pred,
                                                const int* __restrict__ gt) {
    extern __shared__ char sm[];
    float* sS = (float*)(sm + SS_OFF);
    float* sN = (float*)(sm + SN_OFF);
    float* scnt = (float*)(sm + SCNT_OFF);
    int* cursor = (int*)(sm + CUR_OFF);
    unsigned short* sidx = (unsigned short*)(sm + IDX_OFF);
    float* sbinv = (float*)(sm + BINV_OFF);
    const int tid = threadIdx.x;
    const int lane = tid & 31, w = tid >> 5;
    const int k = lane & 15, s = lane >> 4;

    unsigned sm32;
    asm("{ .reg .u64 t; cvta.to.shared.u64 t, %1; cvt.u32.u64 %0, t; }"
        : "=r"(sm32) : "l"(sm));

    for (int i = tid; i < NL * NC; i += BLK1) { sS[i] = 0.f; sN[i] = 0.f; }
    if (tid < NL) scnt[tid] = 0.f;
    __syncthreads();

    issue_tile(sm32, blockIdx.x, 0, pred, gt);
    CP_COMMIT();

    int it = 0;
    for (int t = blockIdx.x; t < NT; t += GRID1, it++) {
        int buf = it & 1;
        int tn = t + GRID1;
        if (tn < NT) {
            issue_tile(sm32, tn, buf ^ 1, pred, gt);
            CP_COMMIT();
            CP_WAIT1();
        } else {
            CP_WAIT0();
        }
        __syncthreads();

        if (tid < NL) cursor[tid] = 0;
        __syncthreads();

        // scatter + norm: 2 voxels/thread; inv-norms stay in registers
        int2 lv = *(const int2*)(sm + GT_OFF(buf) + tid * 8);
        float q0 = 0.f, q1 = 0.f;
        {
            const char* pb = sm + P_OFF(buf) + tid * 8;
            #pragma unroll
            for (int kk = 0; kk < NC; kk++) {
                float2 pp = *(const float2*)(pb + kk * ROWB);
                q0 += pp.x * pp.x;
                q1 += pp.y * pp.y;
            }
        }
        float inv0 = rsqrtf(fmaxf(q0, 1e-30f));
        float inv1 = rsqrtf(fmaxf(q1, 1e-30f));
        int ls[2] = {lv.x, lv.y};
        float iv[2] = {inv0, inv1};
        #pragma unroll
        for (int q = 0; q < 2; q++) {
            int l = ls[q], v = tid * 2 + q;
            float ivq = iv[q];
            int r = atomicAdd(&cursor[l], 1);
            if (r < CAP) {
                sidx[l * CAP + r] = (unsigned short)v;
                sbinv[l * CAP + r] = ivq;
            } else {
                #pragma unroll
                for (int kk = 0; kk < NC; kk++) {
                    float pv = *(const float*)(sm + P_OFF(buf) + kk * ROWB + v * 4);
                    atomicAdd(&sS[l * NC + kk], pv);
                    atomicAdd(&sN[l * NC + kk], pv * ivq);
                }
            }
        }
        __syncthreads();

        // gather: warp w owns labels l % 8 == w; dual accumulation, ILP-4
        const char* pbase = sm + P_OFF(buf) + k * ROWB;
        for (int l = w; l < NL; l += 8) {
            int c = cursor[l];
            int cc = c < CAP ? c : CAP;
            float ar = 0.f, an = 0.f;
            #pragma unroll
            for (int jj = 0; jj < 4; jj++) {
                int i0 = s * 4 + jj * 8;
                if (i0 < cc) {
                    ushort4 v4 = *(const ushort4*)&sidx[l * CAP + i0];
                    float4 n4 = *(const float4*)&sbinv[l * CAP + i0];
                    float p0 = *(const float*)(pbase + (int)v4.x * 4);
                    ar += p0; an += p0 * n4.x;
                    if (i0 + 1 < cc) {
                        float p1 = *(const float*)(pbase + (int)v4.y * 4);
                        ar += p1; an += p1 * n4.y;
                    }
                    if (i0 + 2 < cc) {
                        float p2 = *(const float*)(pbase + (int)v4.z * 4);
                        ar += p2; an += p2 * n4.z;
                    }
                    if (i0 + 3 < cc) {
                        float p3 = *(const float*)(pbase + (int)v4.w * 4);
                        ar += p3; an += p3 * n4.w;
                    }
                }
            }
            ar += __shfl_xor_sync(0xffffffffu, ar, 16);
            an += __shfl_xor_sync(0xffffffffu, an, 16);
            if (s == 0) {
                sS[l * NC + k] += ar;
                sN[l * NC + k] += an;
            }
            if (lane == 0) scnt[l] += (float)c;
        }
        __syncthreads();   // protect buffer + cursor reuse
    }

    for (int i2 = tid; i2 < NL * PCX; i2 += BLK1) {
        int l = i2 / PCX, v = i2 % PCX;
        float r;
        if (v < NC) r = sS[l * NC + v];
        else if (v < 2 * NC) r = sN[l * NC + (v - NC)];
        else r = scnt[l];
        (&g_part[blockIdx.x][0][0])[i2] = r;
    }
}

// ---------------- Reduce partials (double accumulation) ----------------
__global__ void k_reduce() { // grid NL*PCX, block 256
    int l = blockIdx.x / PCX, v = blockIdx.x % PCX;
    double acc = 0.0;
    for (int c = threadIdx.x; c < GRID1; c += 256) acc += (double)g_part[c][l][v];
    acc = blockReduceD(acc);
    if (threadIdx.x == 0) g_red[l][v] = (float)acc;
}

// ---------------- Finish: means, intra, inter, loss ----------------
__global__ void k_finish(float* __restrict__ out) {
    __shared__ float s_cmn[NL - 1][NC];
    int t = threadIdx.x;
    double intra_c = 0.0;
    if (t < NL) {
        float cf = fmaxf(g_red[t][32], 1.f);
        float m[NC];
        float n2 = 0.f;
        #pragma unroll
        for (int kk = 0; kk < NC; kk++) {
            m[kk] = g_red[t][kk] / cf;
            n2 += m[kk] * m[kk];
        }
        float mn = sqrtf(n2);
        if (t >= 1) {
            float inv = 1.f / fmaxf(mn, 1e-8f);
            float dot = 0.f;
            #pragma unroll
            for (int kk = 0; kk < NC; kk++) {
                s_cmn[t - 1][kk] = m[kk] * inv;
                dot += m[kk] * g_red[t][NC + kk];   // dot(m_l, sum of normalized p)
            }
            intra_c = (double)dot / ((double)fmaxf(mn, 1e-30f) * (double)cf);
        }
    }
    __syncthreads();
    double intra = blockReduceD(intra_c);   // valid on thread 0
    __syncthreads();

    double acc = 0.0;
    for (int p = t; p < 1225; p += blockDim.x) {
        int i = 0, rem = p;
        while (rem >= (NL - 2) - i) { rem -= (NL - 2) - i; i++; }
        int j = i + 1 + rem;
        float d = 0.f;
        #pragma unroll
        for (int kk = 0; kk < NC; kk++) d += s_cmn[i][kk] * s_cmn[j][kk];
        d = fminf(fmaxf(d, 0.f), 1.f);
        acc += (double)d;
    }
    __syncthreads();
    double inter = blockReduceD(acc);       // valid on thread 0
    if (t == 0) out[0] = (float)(inter / 1225.0 - intra / (double)(NL - 1));
}

extern "C" void kernel_launch(void* const* d_in, const int* in_sizes, int n_in,
                              void* d_out, int out_size) {
    const float* pred = (const float*)d_in[0];
    const int* gt = (const int*)d_in[1];
    float* out = (float*)d_out;

    cudaFuncSetAttribute(k_fused, cudaFuncAttributeMaxDynamicSharedMemorySize, SMEM1);

    k_fused<<<GRID1, BLK1, SMEM1>>>(pred, gt);
    k_reduce<<<NL * PCX, 256>>>();
    k_finish<<<1, 256>>>(out);
}

// round 9
// speedup vs baseline: 2.5562x; 1.0956x over previous
#include <cuda_runtime.h>
#include <math.h>

#define NL 51
#define NC 16
#define PCX 33          // 16 sums + 16 normsums + count
#define GRID1 296       // 2 CTAs/SM * 148
#define BLK1 512
#define TILE 512
#define NT 8192         // 4194304 voxels / 512
#define ROWB 2064       // staged p row stride (bytes): 512*4 + 16
#define CAP 32

static const long long CH_STRIDE = 1LL << 21;   // floats per channel plane

// dynamic smem layout (bytes)
#define P_OFF(b)   ((b) * 33024)                 // 16 rows * 2064
#define GT_OFF(b)  (66048 + (b) * 2048)
#define IDX_OFF    70144                         // ushort[51][32] = 3264
#define BINV_OFF   73408                         // float[51][32] = 6528
#define CUR_OFF    79936                         // int[51] + pad
#define SS_OFF     80144                         // float[51][16]
#define SN_OFF     83408                         // float[51][16]
#define SCNT_OFF   86672                         // float[51]
#define SMEM1      86912

#define CP_ASYNC16(dst, src) \
    asm volatile("cp.async.cg.shared.global [%0], [%1], 16;\n" :: "r"(dst), "l"(src))
#define CP_COMMIT() asm volatile("cp.async.commit_group;\n" ::: "memory")
#define CP_WAIT1()  asm volatile("cp.async.wait_group 1;\n" ::: "memory")
#define CP_WAIT0()  asm volatile("cp.async.wait_group 0;\n" ::: "memory")

// Scratch — transposed: consecutive CTAs adjacent for coalesced reduce
static __device__ float g_part[NL * PCX][GRID1];
static __device__ float g_red[NL][PCX];

__device__ __forceinline__ double blockReduceD(double v) {
    __shared__ double sh[32];
    int lane = threadIdx.x & 31, w = threadIdx.x >> 5;
    #pragma unroll
    for (int o = 16; o; o >>= 1) v += __shfl_down_sync(0xffffffffu, v, o);
    if (lane == 0) sh[w] = v;
    __syncthreads();
    int nw = (blockDim.x + 31) >> 5;
    v = (threadIdx.x < nw) ? sh[threadIdx.x] : 0.0;
    if (w == 0) {
        #pragma unroll
        for (int o = 16; o; o >>= 1) v += __shfl_down_sync(0xffffffffu, v, o);
    }
    return v; // valid on thread 0
}

__device__ __forceinline__ void issue_tile(unsigned sm32, int t, int buf,
                                           const float* __restrict__ pred,
                                           const int* __restrict__ gt) {
    size_t v0 = (size_t)t * TILE;
    const char* psrc = (const char*)(pred + (v0 >> 21) * (NC * (size_t)CH_STRIDE)
                                          + (v0 & (size_t)(CH_STRIDE - 1)));
    int tid = threadIdx.x;
    #pragma unroll
    for (int it = 0; it < 4; it++) {
        int o = tid + it * BLK1;         // 0..2047
        int k = o >> 7, c = o & 127;     // 128 16B-granules per 512-float row
        unsigned dst = sm32 + P_OFF(buf) + k * ROWB + c * 16;
        const char* src = psrc + (size_t)k * ((size_t)CH_STRIDE * 4) + (size_t)c * 16;
        CP_ASYNC16(dst, src);
    }
    if (tid < 128) {
        unsigned dstg = sm32 + GT_OFF(buf) + tid * 16;
        const char* srcg = (const char*)(gt + v0) + (size_t)tid * 16;
        CP_ASYNC16(dstg, srcg);
    }
}

// ---------- Fused pass: per-label count, sum(p), sum(p/|p|) in ONE data read ----------
__global__ void __launch_bounds__(BLK1, 2) k_fused(const float* __restrict__ pred,
                                                   const int* __restrict__ gt) {
    extern __shared__ char sm[];
    float* sS = (float*)(sm + SS_OFF);
    float* sN = (float*)(sm + SN_OFF);
    float* scnt = (float*)(sm + SCNT_OFF);
    int* cursor = (int*)(sm + CUR_OFF);
    unsigned short* sidx = (unsigned short*)(sm + IDX_OFF);
    float* sbinv = (float*)(sm + BINV_OFF);
    const int tid = threadIdx.x;
    const int lane = tid & 31, w = tid >> 5;
    const int k = lane & 15, s = lane >> 4;

    unsigned sm32;
    asm("{ .reg .u64 t; cvta.to.shared.u64 t, %1; cvt.u32.u64 %0, t; }"
        : "=r"(sm32) : "l"(sm));

    for (int i = tid; i < NL * NC; i += BLK1) { sS[i] = 0.f; sN[i] = 0.f; }
    if (tid < NL) scnt[tid] = 0.f;
    __syncthreads();

    issue_tile(sm32, blockIdx.x, 0, pred, gt);
    CP_COMMIT();

    int it = 0;
    for (int t = blockIdx.x; t < NT; t += GRID1, it++) {
        int buf = it & 1;
        int tn = t + GRID1;
        if (tn < NT) {
            issue_tile(sm32, tn, buf ^ 1, pred, gt);
            CP_COMMIT();
            CP_WAIT1();
        } else {
            CP_WAIT0();
        }
        __syncthreads();

        if (tid < NL) cursor[tid] = 0;
        __syncthreads();

        // scatter + norm: 1 voxel/thread; inv-norm stays in registers
        int l = *(const int*)(sm + GT_OFF(buf) + tid * 4);
        float q = 0.f;
        {
            const char* pb = sm + P_OFF(buf) + tid * 4;
            #pragma unroll
            for (int kk = 0; kk < NC; kk++) {
                float pp = *(const float*)(pb + kk * ROWB);
                q += pp * pp;
            }
        }
        float inv = rsqrtf(fmaxf(q, 1e-30f));
        {
            int r = atomicAdd(&cursor[l], 1);
            if (r < CAP) {
                sidx[l * CAP + r] = (unsigned short)tid;
                sbinv[l * CAP + r] = inv;
            } else {
                #pragma unroll
                for (int kk = 0; kk < NC; kk++) {
                    float pv = *(const float*)(sm + P_OFF(buf) + kk * ROWB + tid * 4);
                    atomicAdd(&sS[l * NC + kk], pv);
                    atomicAdd(&sN[l * NC + kk], pv * inv);
                }
            }
        }
        __syncthreads();

        // gather: warp w owns labels l % 16 == w; dual accumulation, ILP-4
        const char* pbase = sm + P_OFF(buf) + k * ROWB;
        for (int l2 = w; l2 < NL; l2 += 16) {
            int c = cursor[l2];
            int cc = c < CAP ? c : CAP;
            float ar = 0.f, an = 0.f;
            #pragma unroll
            for (int jj = 0; jj < 4; jj++) {
                int i0 = s * 4 + jj * 8;
                if (i0 < cc) {
                    ushort4 v4 = *(const ushort4*)&sidx[l2 * CAP + i0];
                    float4 n4 = *(const float4*)&sbinv[l2 * CAP + i0];
                    float p0 = *(const float*)(pbase + (int)v4.x * 4);
                    ar += p0; an += p0 * n4.x;
                    if (i0 + 1 < cc) {
                        float p1 = *(const float*)(pbase + (int)v4.y * 4);
                        ar += p1; an += p1 * n4.y;
                    }
                    if (i0 + 2 < cc) {
                        float p2 = *(const float*)(pbase + (int)v4.z * 4);
                        ar += p2; an += p2 * n4.z;
                    }
                    if (i0 + 3 < cc) {
                        float p3 = *(const float*)(pbase + (int)v4.w * 4);
                        ar += p3; an += p3 * n4.w;
                    }
                }
            }
            ar += __shfl_xor_sync(0xffffffffu, ar, 16);
            an += __shfl_xor_sync(0xffffffffu, an, 16);
            if (s == 0) {
                sS[l2 * NC + k] += ar;
                sN[l2 * NC + k] += an;
            }
            if (lane == 0) scnt[l2] += (float)c;
        }
        __syncthreads();   // protect buffer + cursor reuse
    }

    for (int i2 = tid; i2 < NL * PCX; i2 += BLK1) {
        int l = i2 / PCX, v = i2 % PCX;
        float r;
        if (v < NC) r = sS[l * NC + v];
        else if (v < 2 * NC) r = sN[l * NC + (v - NC)];
        else r = scnt[l];
        g_part[i2][blockIdx.x] = r;
    }
}

// ---------------- Reduce partials (double accumulation, coalesced) ----------------
__global__ void k_reduce() { // grid NL*PCX, block 128
    double acc = 0.0;
    for (int c = threadIdx.x; c < GRID1; c += 128) acc += (double)g_part[blockIdx.x][c];
    acc = blockReduceD(acc);
    if (threadIdx.x == 0) g_red[blockIdx.x / PCX][blockIdx.x % PCX] = (float)acc;
}

// ---------------- Finish: means, intra, inter, loss ----------------
__global__ void k_finish(float* __restrict__ out) {
    __shared__ float s_cmn[NL - 1][NC];
    int t = threadIdx.x;
    double intra_c = 0.0;
    if (t < NL) {
        float cf = fmaxf(g_red[t][32], 1.f);
        float m[NC];
        float n2 = 0.f;
        #pragma unroll
        for (int kk = 0; kk < NC; kk++) {
            m[kk] = g_red[t][kk] / cf;
            n2 += m[kk] * m[kk];
        }
        float mn = sqrtf(n2);
        if (t >= 1) {
            float inv = 1.f / fmaxf(mn, 1e-8f);
            float dot = 0.f;
            #pragma unroll
            for (int kk = 0; kk < NC; kk++) {
                s_cmn[t - 1][kk] = m[kk] * inv;
                dot += m[kk] * g_red[t][NC + kk];   // dot(m_l, sum of normalized p)
            }
            intra_c = (double)dot / ((double)fmaxf(mn, 1e-30f) * (double)cf);
        }
    }
    __syncthreads();
    double intra = blockReduceD(intra_c);   // valid on thread 0
    __syncthreads();

    double acc = 0.0;
    for (int p = t; p < 1225; p += blockDim.x) {
        int i = 0, rem = p;
        while (rem >= (NL - 2) - i) { rem -= (NL - 2) - i; i++; }
        int j = i + 1 + rem;
        float d = 0.f;
        #pragma unroll
        for (int kk = 0; kk < NC; kk++) d += s_cmn[i][kk] * s_cmn[j][kk];
        d = fminf(fmaxf(d, 0.f), 1.f);
        acc += (double)d;
    }
    __syncthreads();
    double inter = blockReduceD(acc);       // valid on thread 0
    if (t == 0) out[0] = (float)(inter / 1225.0 - intra / (double)(NL - 1));
}

extern "C" void kernel_launch(void* const* d_in, const int* in_sizes, int n_in,
                              void* d_out, int out_size) {
    const float* pred = (const float*)d_in[0];
    const int* gt = (const int*)d_in[1];
    float* out = (float*)d_out;

    cudaFuncSetAttribute(k_fused, cudaFuncAttributeMaxDynamicSharedMemorySize, SMEM1);

    k_fused<<<GRID1, BLK1, SMEM1>>>(pred, gt);
    k_reduce<<<NL * PCX, 128>>>();
    k_finish<<<1, 256>>>(out);
}